// round 15
// baseline (speedup 1.0000x reference)
#include <cuda_runtime.h>
#include <cuda_fp16.h>
#include <cstdint>

// ---------------------------------------------------------------------------
// Shapes: inputs[16384,512] f32, adj[16384,16384] f32, W[512,128] f32
//   X   = inputs @ W   (2.1 GF)     out = adj @ X   (68.7 GF)
// Engine: mma.sync.aligned.m16n8k16.row.col.f32.f16.f16.f32.
// R15: R14 (persistent split-K, best 320.3us) + adj loads via ld.global.cg
// (L2-only, L1 bypass). Profile showed L1=87.8% binding with tensor at only
// 37.6%: the stream-once adj LDGs were burning ~14% of the binding pipe's
// wavefront slots. All else identical to R14.
// ---------------------------------------------------------------------------

#define M_DIM 16384
#define N_DIM 128
#define K1    512

__device__ __align__(16) __half g_WtH[N_DIM * K1];         // W^T fp16 [n][k]
__device__ __align__(16) __half g_XtH[(long)N_DIM * M_DIM];// X^T fp16 [n][m] (4 MB)
__device__ int g_ctr;                                      // unit counter

#define NTHREADS 512
#define BK 64
#define STAGES 4
#define ROW_B 144                                 // 128 B data + 16 B pad
#define TILE_B (128 * ROW_B)                      // 18432 B per tile
#define SMEM_BYTES (STAGES * 2 * TILE_B)          // 147456 B

#define KCH_ITERS 32                              // iters per k-chunk
#define KCH_COLS  (KCH_ITERS * BK)                // 2048
#define NKCH      (M_DIM / KCH_COLS)              // 8
#define NUNITS    ((M_DIM / 128) * NKCH)          // 1024
#define GRID2     148

// ---------------- helpers ----------------
__device__ __forceinline__ uint32_t smem_u32(const void* p) {
    uint32_t a;
    asm("{ .reg .u64 t; cvta.to.shared.u64 t, %1; cvt.u32.u64 %0, t; }"
        : "=r"(a) : "l"(p));
    return a;
}
#define CP_ASYNC16(dst, src) \
    asm volatile("cp.async.cg.shared.global [%0], [%1], 16;" :: "r"(dst), "l"(src) : "memory")
#define CP_COMMIT()  asm volatile("cp.async.commit_group;" ::: "memory")
#define CP_WAIT2()   asm volatile("cp.async.wait_group 2;" ::: "memory")
#define CP_WAIT0()   asm volatile("cp.async.wait_group 0;" ::: "memory")

__device__ __forceinline__ void mma_f16(float c[4], const uint32_t a[4], const uint32_t b[2]) {
    asm volatile(
        "mma.sync.aligned.m16n8k16.row.col.f32.f16.f16.f32 "
        "{%0,%1,%2,%3}, {%4,%5,%6,%7}, {%8,%9}, {%0,%1,%2,%3};"
        : "+f"(c[0]), "+f"(c[1]), "+f"(c[2]), "+f"(c[3])
        : "r"(a[0]), "r"(a[1]), "r"(a[2]), "r"(a[3]), "r"(b[0]), "r"(b[1]));
}
__device__ __forceinline__ void ldsm4(uint32_t r[4], uint32_t addr) {
    asm volatile("ldmatrix.sync.aligned.m8n8.x4.shared.b16 {%0,%1,%2,%3}, [%4];"
                 : "=r"(r[0]), "=r"(r[1]), "=r"(r[2]), "=r"(r[3]) : "r"(addr));
}
__device__ __forceinline__ uint32_t pack_h2(float x, float y) {
    __half2 h = __float22half2_rn(make_float2(x, y));
    return *(uint32_t*)&h;
}
// L1-bypassing streaming load (L2 only): adj is read exactly once.
__device__ __forceinline__ float4 ldg_cg4(const float* __restrict__ p) {
    float4 v;
    asm volatile("ld.global.cg.v4.f32 {%0,%1,%2,%3}, [%4];"
                 : "=f"(v.x), "=f"(v.y), "=f"(v.z), "=f"(v.w) : "l"(p));
    return v;
}

// ---------------- producers ----------------
__device__ __forceinline__ void load_B_tile(
    uint32_t ts, const __half* __restrict__ T, long ldt, int k0, int tid)
{
    #pragma unroll
    for (int j = 0; j < 2; j++) {
        int idx = tid + j * NTHREADS;          // 0..1023
        int row = idx >> 3, cc = idx & 7;
        CP_ASYNC16(ts + (uint32_t)(row * ROW_B + cc * 16),
                   T + (long)row * ldt + k0 + cc * 8);
    }
}
__device__ __forceinline__ void ldg_A(float4 rb[4], const float* __restrict__ A,
                                      long lda, int k0, int tid)
{
    const float* p = A + (long)(tid >> 2) * lda + k0 + (tid & 3) * 16;
    #pragma unroll
    for (int q = 0; q < 4; q++) rb[q] = ldg_cg4(p + q * 4);
}
__device__ __forceinline__ void sts_A_cvt(uint32_t as, const float4 rb[4], int tid)
{
    int row = tid >> 2, c = tid & 3;
    int s = (row >> 3) & 3;
    uint32_t off = as + (uint32_t)(row * ROW_B + ((c ^ s) * 32));
    uint32_t p0 = pack_h2(rb[0].x, rb[0].y), p1 = pack_h2(rb[0].z, rb[0].w);
    uint32_t p2 = pack_h2(rb[1].x, rb[1].y), p3 = pack_h2(rb[1].z, rb[1].w);
    uint32_t p4 = pack_h2(rb[2].x, rb[2].y), p5 = pack_h2(rb[2].z, rb[2].w);
    uint32_t p6 = pack_h2(rb[3].x, rb[3].y), p7 = pack_h2(rb[3].z, rb[3].w);
    asm volatile("st.shared.v4.b32 [%0], {%1,%2,%3,%4};"
                 :: "r"(off), "r"(p0), "r"(p1), "r"(p2), "r"(p3) : "memory");
    asm volatile("st.shared.v4.b32 [%0], {%1,%2,%3,%4};"
                 :: "r"(off + 16), "r"(p4), "r"(p5), "r"(p6), "r"(p7) : "memory");
}

// ---------------- compute ----------------
__device__ __forceinline__ void compute_stage(
    uint32_t sA, uint32_t sB,
    uint32_t Aoff0, uint32_t Aoff1, uint32_t sft0, uint32_t sft1,
    uint32_t Boff, float acc[2][4][4])
{
    #pragma unroll
    for (int kk = 0; kk < 4; kk++) {
        uint32_t a[2][4], b[2][4];
        ldsm4(a[0], sA + Aoff0 + (((uint32_t)(kk << 5)) ^ sft0));
        ldsm4(a[1], sA + Aoff1 + (((uint32_t)(kk << 5)) ^ sft1));
        ldsm4(b[0], sB + Boff + kk * 32);
        ldsm4(b[1], sB + Boff + 16 * ROW_B + kk * 32);
        #pragma unroll
        for (int mt = 0; mt < 2; mt++)
            #pragma unroll
            for (int nt = 0; nt < 4; nt++)
                mma_f16(acc[mt][nt], a[mt], &b[nt >> 1][(nt & 1) * 2]);
    }
}

// ---------------- mainloop ----------------
template <int NITER>
__device__ __forceinline__ void gemm_mainloop(
    const float* __restrict__ A, long lda,
    const __half* __restrict__ B, long ldb,
    float acc[2][4][4], char* smem)
{
    const int tid = threadIdx.x;
    const int wid = tid >> 5, lid = tid & 31;
    const int wr = wid >> 2, wc = wid & 3;
    const uint32_t sbase = smem_u32(smem);
    const uint32_t bregion = sbase + STAGES * TILE_B;

    const int row0 = wr * 32 + (lid & 15);
    const int row1 = row0 + 16;
    const uint32_t sub16 = ((lid >> 4) & 1) * 16;
    const uint32_t Aoff0 = (uint32_t)(row0 * ROW_B) + sub16;
    const uint32_t Aoff1 = (uint32_t)(row1 * ROW_B) + sub16;
    const uint32_t sft0 = (uint32_t)(((row0 >> 3) & 3) << 5);
    const uint32_t sft1 = (uint32_t)(((row1 >> 3) & 3) << 5);
    const uint32_t Boff = (uint32_t)((wc * 32 + ((lid >> 4) & 1) * 8 + (lid & 7)) * ROW_B
                                     + ((lid >> 3) & 1) * 16);

    #pragma unroll
    for (int mt = 0; mt < 2; mt++)
        #pragma unroll
        for (int nt = 0; nt < 4; nt++)
            #pragma unroll
            for (int r = 0; r < 4; r++) acc[mt][nt][r] = 0.0f;

    float4 rb[4];

    ldg_A(rb, A, lda, 0, tid);
    load_B_tile(bregion, B, ldb, 0, tid);
    CP_COMMIT();                               // g0
    sts_A_cvt(sbase, rb, tid);
    ldg_A(rb, A, lda, BK, tid);
    if (2 < NITER) load_B_tile(bregion + TILE_B, B, ldb, BK, tid);
    CP_COMMIT();                               // g1
    if (2 < NITER) load_B_tile(bregion + 2 * TILE_B, B, ldb, 2 * BK, tid);
    else if (1 < NITER) load_B_tile(bregion + TILE_B, B, ldb, BK, tid);
    CP_COMMIT();                               // g2
    CP_WAIT2();
    __syncthreads();

    #pragma unroll 1
    for (int i = 0; i < NITER; i++) {
        if (i + 1 < NITER)
            sts_A_cvt(sbase + ((i + 1) % STAGES) * TILE_B, rb, tid);
        if (i + 2 < NITER)
            ldg_A(rb, A, lda, (i + 2) * BK, tid);
        if (i + 3 < NITER)
            load_B_tile(bregion + ((i + 3) % STAGES) * TILE_B, B, ldb, (i + 3) * BK, tid);
        CP_COMMIT();
        int s = i % STAGES;
        compute_stage(sbase + s * TILE_B, bregion + s * TILE_B,
                      Aoff0, Aoff1, sft0, sft1, Boff, acc);
        if (i + 1 < NITER) { CP_WAIT2(); }
        else               { CP_WAIT0(); }
        __syncthreads();
    }
}

// ---------------- prepass: W^T fp16 ----------------
__global__ __launch_bounds__(256) void wt_kernel(const float* __restrict__ w) {
    int i = blockIdx.x * blockDim.x + threadIdx.x;
    if (i < N_DIM * K1) {
        int n = i / K1, k = i % K1;
        g_WtH[i] = __float2half_rn(w[(long)k * N_DIM + n]);
    }
}

// ---------------- zero out + reset counter ----------------
__global__ __launch_bounds__(256) void zero_kernel(float* __restrict__ out) {
    if (blockIdx.x == 0 && threadIdx.x == 0) g_ctr = 0;
    const long n4 = (long)M_DIM * N_DIM / 4;
    for (long i = blockIdx.x * blockDim.x + threadIdx.x; i < n4;
         i += (long)gridDim.x * blockDim.x)
        ((float4*)out)[i] = make_float4(0.f, 0.f, 0.f, 0.f);
}

// ---------------- GEMM1: XtH = (inputs @ W)^T fp16 ----------------
__global__ __launch_bounds__(NTHREADS, 1) void gemm1_kernel(const float* __restrict__ inputs) {
    extern __shared__ char smem[];
    float acc[2][4][4];
    const int m0 = blockIdx.x * 128;

    gemm_mainloop<K1 / BK>(inputs + (long)m0 * K1, K1, g_WtH, K1, acc, smem);

    const int wid = threadIdx.x >> 5, lid = threadIdx.x & 31;
    const int wr = wid >> 2, wc = wid & 3, gID = lid >> 2, tig = lid & 3;
    #pragma unroll
    for (int mt = 0; mt < 2; mt++)
        #pragma unroll
        for (int nt = 0; nt < 4; nt++) {
            int r = m0 + wr * 32 + mt * 16 + gID;
            int c = wc * 32 + nt * 8 + tig * 2;
            g_XtH[(long)c * M_DIM + r]           = __float2half_rn(acc[mt][nt][0]);
            g_XtH[(long)(c + 1) * M_DIM + r]     = __float2half_rn(acc[mt][nt][1]);
            g_XtH[(long)c * M_DIM + r + 8]       = __float2half_rn(acc[mt][nt][2]);
            g_XtH[(long)(c + 1) * M_DIM + r + 8] = __float2half_rn(acc[mt][nt][3]);
        }
}

// ---------------- GEMM2: persistent split-K, RED epilogue ----------------
__global__ __launch_bounds__(NTHREADS, 1) void gemm2_kernel(const float* __restrict__ adj,
                                                            float* __restrict__ out) {
    extern __shared__ char smem[];
    __shared__ int s_unit;
    float acc[2][4][4];

    const int tid = threadIdx.x;
    const int wid = tid >> 5, lid = tid & 31;
    const int wr = wid >> 2, wc = wid & 3, gID = lid >> 2, tig = lid & 3;

    for (;;) {
        if (tid == 0) s_unit = atomicAdd(&g_ctr, 1);
        __syncthreads();
        const int u = s_unit;
        __syncthreads();
        if (u >= NUNITS) break;

        const int mt_tile = u >> 3;            // 0..127
        const int kc      = u & 7;             // 0..7
        const long m0 = (long)mt_tile * 128;
        const long k0 = (long)kc * KCH_COLS;

        gemm_mainloop<KCH_ITERS>(adj + m0 * M_DIM + k0, M_DIM,
                                 g_XtH + k0, M_DIM, acc, smem);

        #pragma unroll
        for (int mt = 0; mt < 2; mt++)
            #pragma unroll
            for (int nt = 0; nt < 4; nt++) {
                long r = m0 + wr * 32 + mt * 16 + gID;
                int  c = wc * 32 + nt * 8 + tig * 2;
                atomicAdd(&out[r * N_DIM + c],           acc[mt][nt][0]);
                atomicAdd(&out[r * N_DIM + c + 1],       acc[mt][nt][1]);
                atomicAdd(&out[(r + 8) * N_DIM + c],     acc[mt][nt][2]);
                atomicAdd(&out[(r + 8) * N_DIM + c + 1], acc[mt][nt][3]);
            }
    }
}

// ---------------- launch ----------------
extern "C" void kernel_launch(void* const* d_in, const int* in_sizes, int n_in,
                              void* d_out, int out_size)
{
    const float* inputs  = (const float*)d_in[0];
    const float* adj     = (const float*)d_in[1];
    const float* weights = (const float*)d_in[2];
    float* out = (float*)d_out;

    cudaFuncSetAttribute(gemm1_kernel, cudaFuncAttributeMaxDynamicSharedMemorySize, SMEM_BYTES);
    cudaFuncSetAttribute(gemm2_kernel, cudaFuncAttributeMaxDynamicSharedMemorySize, SMEM_BYTES);

    wt_kernel<<<(N_DIM * K1 + 255) / 256, 256>>>(weights);
    gemm1_kernel<<<M_DIM / 128, NTHREADS, SMEM_BYTES>>>(inputs);
    zero_kernel<<<512, 256>>>(out);
    gemm2_kernel<<<GRID2, NTHREADS, SMEM_BYTES>>>(adj, out);
}

// round 16
// speedup vs baseline: 1.5081x; 1.5081x over previous
#include <cuda_runtime.h>
#include <cuda_fp16.h>
#include <cstdint>

// ---------------------------------------------------------------------------
// Shapes: inputs[16384,512] f32, adj[16384,16384] f32, W[512,128] f32
//   X   = inputs @ W   (2.1 GF)     out = adj @ X   (68.7 GF)
// Engine: mma.sync.aligned.m16n8k16.row.col.f32.f16.f16.f32.
// R16: full revert of R15's ld.global.cg (latency-bound disaster: every pipe
// utilization fell proportionally). Base = R14 (best, 320.3us: persistent
// split-K grid=148, STAGES=4 ring, A-chunk swizzle). Micro-cuts only:
//  - epilogue uses red.global.add.v2.f32 (sm_90+ vector RED, halves atomics)
//  - one redundant __syncthreads removed from the unit-fetch sequence
// ---------------------------------------------------------------------------

#define M_DIM 16384
#define N_DIM 128
#define K1    512

__device__ __align__(16) __half g_WtH[N_DIM * K1];         // W^T fp16 [n][k]
__device__ __align__(16) __half g_XtH[(long)N_DIM * M_DIM];// X^T fp16 [n][m] (4 MB)
__device__ int g_ctr;                                      // unit counter

#define NTHREADS 512
#define BK 64
#define STAGES 4
#define ROW_B 144                                 // 128 B data + 16 B pad
#define TILE_B (128 * ROW_B)                      // 18432 B per tile
#define SMEM_BYTES (STAGES * 2 * TILE_B)          // 147456 B

#define KCH_ITERS 32                              // iters per k-chunk
#define KCH_COLS  (KCH_ITERS * BK)                // 2048
#define NKCH      (M_DIM / KCH_COLS)              // 8
#define NUNITS    ((M_DIM / 128) * NKCH)          // 1024
#define GRID2     148

// ---------------- helpers ----------------
__device__ __forceinline__ uint32_t smem_u32(const void* p) {
    uint32_t a;
    asm("{ .reg .u64 t; cvta.to.shared.u64 t, %1; cvt.u32.u64 %0, t; }"
        : "=r"(a) : "l"(p));
    return a;
}
#define CP_ASYNC16(dst, src) \
    asm volatile("cp.async.cg.shared.global [%0], [%1], 16;" :: "r"(dst), "l"(src) : "memory")
#define CP_COMMIT()  asm volatile("cp.async.commit_group;" ::: "memory")
#define CP_WAIT2()   asm volatile("cp.async.wait_group 2;" ::: "memory")
#define CP_WAIT0()   asm volatile("cp.async.wait_group 0;" ::: "memory")

__device__ __forceinline__ void mma_f16(float c[4], const uint32_t a[4], const uint32_t b[2]) {
    asm volatile(
        "mma.sync.aligned.m16n8k16.row.col.f32.f16.f16.f32 "
        "{%0,%1,%2,%3}, {%4,%5,%6,%7}, {%8,%9}, {%0,%1,%2,%3};"
        : "+f"(c[0]), "+f"(c[1]), "+f"(c[2]), "+f"(c[3])
        : "r"(a[0]), "r"(a[1]), "r"(a[2]), "r"(a[3]), "r"(b[0]), "r"(b[1]));
}
__device__ __forceinline__ void ldsm4(uint32_t r[4], uint32_t addr) {
    asm volatile("ldmatrix.sync.aligned.m8n8.x4.shared.b16 {%0,%1,%2,%3}, [%4];"
                 : "=r"(r[0]), "=r"(r[1]), "=r"(r[2]), "=r"(r[3]) : "r"(addr));
}
__device__ __forceinline__ uint32_t pack_h2(float x, float y) {
    __half2 h = __float22half2_rn(make_float2(x, y));
    return *(uint32_t*)&h;
}
// Vectorized no-return global reduction (sm_90+): out[0]+=x, out[1]+=y.
__device__ __forceinline__ void red_add_v2(float* p, float x, float y) {
    asm volatile("red.global.add.v2.f32 [%0], {%1, %2};"
                 :: "l"(p), "f"(x), "f"(y) : "memory");
}

// ---------------- producers (R14) ----------------
__device__ __forceinline__ void load_B_tile(
    uint32_t ts, const __half* __restrict__ T, long ldt, int k0, int tid)
{
    #pragma unroll
    for (int j = 0; j < 2; j++) {
        int idx = tid + j * NTHREADS;          // 0..1023
        int row = idx >> 3, cc = idx & 7;
        CP_ASYNC16(ts + (uint32_t)(row * ROW_B + cc * 16),
                   T + (long)row * ldt + k0 + cc * 8);
    }
}
__device__ __forceinline__ void ldg_A(float4 rb[4], const float* __restrict__ A,
                                      long lda, int k0, int tid)
{
    const float* p = A + (long)(tid >> 2) * lda + k0 + (tid & 3) * 16;
    #pragma unroll
    for (int q = 0; q < 4; q++) rb[q] = *(const float4*)(p + q * 4);
}
__device__ __forceinline__ void sts_A_cvt(uint32_t as, const float4 rb[4], int tid)
{
    int row = tid >> 2, c = tid & 3;
    int s = (row >> 3) & 3;
    uint32_t off = as + (uint32_t)(row * ROW_B + ((c ^ s) * 32));
    uint32_t p0 = pack_h2(rb[0].x, rb[0].y), p1 = pack_h2(rb[0].z, rb[0].w);
    uint32_t p2 = pack_h2(rb[1].x, rb[1].y), p3 = pack_h2(rb[1].z, rb[1].w);
    uint32_t p4 = pack_h2(rb[2].x, rb[2].y), p5 = pack_h2(rb[2].z, rb[2].w);
    uint32_t p6 = pack_h2(rb[3].x, rb[3].y), p7 = pack_h2(rb[3].z, rb[3].w);
    asm volatile("st.shared.v4.b32 [%0], {%1,%2,%3,%4};"
                 :: "r"(off), "r"(p0), "r"(p1), "r"(p2), "r"(p3) : "memory");
    asm volatile("st.shared.v4.b32 [%0], {%1,%2,%3,%4};"
                 :: "r"(off + 16), "r"(p4), "r"(p5), "r"(p6), "r"(p7) : "memory");
}

// ---------------- compute (R14) ----------------
__device__ __forceinline__ void compute_stage(
    uint32_t sA, uint32_t sB,
    uint32_t Aoff0, uint32_t Aoff1, uint32_t sft0, uint32_t sft1,
    uint32_t Boff, float acc[2][4][4])
{
    #pragma unroll
    for (int kk = 0; kk < 4; kk++) {
        uint32_t a[2][4], b[2][4];
        ldsm4(a[0], sA + Aoff0 + (((uint32_t)(kk << 5)) ^ sft0));
        ldsm4(a[1], sA + Aoff1 + (((uint32_t)(kk << 5)) ^ sft1));
        ldsm4(b[0], sB + Boff + kk * 32);
        ldsm4(b[1], sB + Boff + 16 * ROW_B + kk * 32);
        #pragma unroll
        for (int mt = 0; mt < 2; mt++)
            #pragma unroll
            for (int nt = 0; nt < 4; nt++)
                mma_f16(acc[mt][nt], a[mt], &b[nt >> 1][(nt & 1) * 2]);
    }
}

// ---------------- mainloop (R14) ----------------
template <int NITER>
__device__ __forceinline__ void gemm_mainloop(
    const float* __restrict__ A, long lda,
    const __half* __restrict__ B, long ldb,
    float acc[2][4][4], char* smem)
{
    const int tid = threadIdx.x;
    const int wid = tid >> 5, lid = tid & 31;
    const int wr = wid >> 2, wc = wid & 3;
    const uint32_t sbase = smem_u32(smem);
    const uint32_t bregion = sbase + STAGES * TILE_B;

    const int row0 = wr * 32 + (lid & 15);
    const int row1 = row0 + 16;
    const uint32_t sub16 = ((lid >> 4) & 1) * 16;
    const uint32_t Aoff0 = (uint32_t)(row0 * ROW_B) + sub16;
    const uint32_t Aoff1 = (uint32_t)(row1 * ROW_B) + sub16;
    const uint32_t sft0 = (uint32_t)(((row0 >> 3) & 3) << 5);
    const uint32_t sft1 = (uint32_t)(((row1 >> 3) & 3) << 5);
    const uint32_t Boff = (uint32_t)((wc * 32 + ((lid >> 4) & 1) * 8 + (lid & 7)) * ROW_B
                                     + ((lid >> 3) & 1) * 16);

    #pragma unroll
    for (int mt = 0; mt < 2; mt++)
        #pragma unroll
        for (int nt = 0; nt < 4; nt++)
            #pragma unroll
            for (int r = 0; r < 4; r++) acc[mt][nt][r] = 0.0f;

    float4 rb[4];

    ldg_A(rb, A, lda, 0, tid);
    load_B_tile(bregion, B, ldb, 0, tid);
    CP_COMMIT();                               // g0
    sts_A_cvt(sbase, rb, tid);
    ldg_A(rb, A, lda, BK, tid);
    if (2 < NITER) load_B_tile(bregion + TILE_B, B, ldb, BK, tid);
    CP_COMMIT();                               // g1
    if (2 < NITER) load_B_tile(bregion + 2 * TILE_B, B, ldb, 2 * BK, tid);
    else if (1 < NITER) load_B_tile(bregion + TILE_B, B, ldb, BK, tid);
    CP_COMMIT();                               // g2
    CP_WAIT2();
    __syncthreads();

    #pragma unroll 1
    for (int i = 0; i < NITER; i++) {
        if (i + 1 < NITER)
            sts_A_cvt(sbase + ((i + 1) % STAGES) * TILE_B, rb, tid);
        if (i + 2 < NITER)
            ldg_A(rb, A, lda, (i + 2) * BK, tid);
        if (i + 3 < NITER)
            load_B_tile(bregion + ((i + 3) % STAGES) * TILE_B, B, ldb, (i + 3) * BK, tid);
        CP_COMMIT();
        int s = i % STAGES;
        compute_stage(sbase + s * TILE_B, bregion + s * TILE_B,
                      Aoff0, Aoff1, sft0, sft1, Boff, acc);
        if (i + 1 < NITER) { CP_WAIT2(); }
        else               { CP_WAIT0(); }
        __syncthreads();
    }
}

// ---------------- prepass: W^T fp16 ----------------
__global__ __launch_bounds__(256) void wt_kernel(const float* __restrict__ w) {
    int i = blockIdx.x * blockDim.x + threadIdx.x;
    if (i < N_DIM * K1) {
        int n = i / K1, k = i % K1;
        g_WtH[i] = __float2half_rn(w[(long)k * N_DIM + n]);
    }
}

// ---------------- zero out + reset counter ----------------
__global__ __launch_bounds__(256) void zero_kernel(float* __restrict__ out) {
    if (blockIdx.x == 0 && threadIdx.x == 0) g_ctr = 0;
    const long n4 = (long)M_DIM * N_DIM / 4;
    for (long i = blockIdx.x * blockDim.x + threadIdx.x; i < n4;
         i += (long)gridDim.x * blockDim.x)
        ((float4*)out)[i] = make_float4(0.f, 0.f, 0.f, 0.f);
}

// ---------------- GEMM1: XtH = (inputs @ W)^T fp16 ----------------
__global__ __launch_bounds__(NTHREADS, 1) void gemm1_kernel(const float* __restrict__ inputs) {
    extern __shared__ char smem[];
    float acc[2][4][4];
    const int m0 = blockIdx.x * 128;

    gemm_mainloop<K1 / BK>(inputs + (long)m0 * K1, K1, g_WtH, K1, acc, smem);

    const int wid = threadIdx.x >> 5, lid = threadIdx.x & 31;
    const int wr = wid >> 2, wc = wid & 3, gID = lid >> 2, tig = lid & 3;
    #pragma unroll
    for (int mt = 0; mt < 2; mt++)
        #pragma unroll
        for (int nt = 0; nt < 4; nt++) {
            int r = m0 + wr * 32 + mt * 16 + gID;
            int c = wc * 32 + nt * 8 + tig * 2;
            g_XtH[(long)c * M_DIM + r]           = __float2half_rn(acc[mt][nt][0]);
            g_XtH[(long)(c + 1) * M_DIM + r]     = __float2half_rn(acc[mt][nt][1]);
            g_XtH[(long)c * M_DIM + r + 8]       = __float2half_rn(acc[mt][nt][2]);
            g_XtH[(long)(c + 1) * M_DIM + r + 8] = __float2half_rn(acc[mt][nt][3]);
        }
}

// ---------------- GEMM2: persistent split-K, vector-RED epilogue ------------
__global__ __launch_bounds__(NTHREADS, 1) void gemm2_kernel(const float* __restrict__ adj,
                                                            float* __restrict__ out) {
    extern __shared__ char smem[];
    __shared__ int s_unit;
    float acc[2][4][4];

    const int tid = threadIdx.x;
    const int wid = tid >> 5, lid = tid & 31;
    const int wr = wid >> 2, wc = wid & 3, gID = lid >> 2, tig = lid & 3;

    for (;;) {
        if (tid == 0) s_unit = atomicAdd(&g_ctr, 1);
        __syncthreads();
        const int u = s_unit;
        // no second barrier: u is a register copy; the mainloop's first
        // __syncthreads gates tid0 from re-writing s_unit before all read it.
        if (u >= NUNITS) break;

        const int mt_tile = u >> 3;            // 0..127
        const int kc      = u & 7;             // 0..7
        const long m0 = (long)mt_tile * 128;
        const long k0 = (long)kc * KCH_COLS;

        gemm_mainloop<KCH_ITERS>(adj + m0 * M_DIM + k0, M_DIM,
                                 g_XtH + k0, M_DIM, acc, smem);

        #pragma unroll
        for (int mt = 0; mt < 2; mt++)
            #pragma unroll
            for (int nt = 0; nt < 4; nt++) {
                long r = m0 + wr * 32 + mt * 16 + gID;
                int  c = wc * 32 + nt * 8 + tig * 2;
                red_add_v2(&out[r * N_DIM + c],       acc[mt][nt][0], acc[mt][nt][1]);
                red_add_v2(&out[(r + 8) * N_DIM + c], acc[mt][nt][2], acc[mt][nt][3]);
            }
    }
}

// ---------------- launch ----------------
extern "C" void kernel_launch(void* const* d_in, const int* in_sizes, int n_in,
                              void* d_out, int out_size)
{
    const float* inputs  = (const float*)d_in[0];
    const float* adj     = (const float*)d_in[1];
    const float* weights = (const float*)d_in[2];
    float* out = (float*)d_out;

    cudaFuncSetAttribute(gemm1_kernel, cudaFuncAttributeMaxDynamicSharedMemorySize, SMEM_BYTES);
    cudaFuncSetAttribute(gemm2_kernel, cudaFuncAttributeMaxDynamicSharedMemorySize, SMEM_BYTES);

    wt_kernel<<<(N_DIM * K1 + 255) / 256, 256>>>(weights);
    gemm1_kernel<<<M_DIM / 128, NTHREADS, SMEM_BYTES>>>(inputs);
    zero_kernel<<<512, 256>>>(out);
    gemm2_kernel<<<GRID2, NTHREADS, SMEM_BYTES>>>(adj, out);
}

// round 17
// speedup vs baseline: 1.6137x; 1.0700x over previous
#include <cuda_runtime.h>
#include <cuda_fp16.h>
#include <cstdint>

// ---------------------------------------------------------------------------
// Shapes: inputs[16384,512] f32, adj[16384,16384] f32, W[512,128] f32
//   X   = inputs @ W   (2.1 GF)     out = adj @ X   (68.7 GF)
// Engine: mma.sync.aligned.m16n8k16.row.col.f32.f16.f16.f32.
// R17: R16 base (best 317.9). gemm2 work units -> static CONTIGUOUS ranges:
// CTA c owns global k-iters [222c, 222c+222) of 128x256 total -> <=2 mainloop
// segments per CTA (was 7 refills via atomic units). Mainloop takes runtime
// NITER; B-stage s always in cp.async group s (small-NITER safe). wt+zero
// fused into one prep kernel. Epilogue red.global.add.v2.f32 as in R16.
// ---------------------------------------------------------------------------

#define M_DIM 16384
#define N_DIM 128
#define K1    512

__device__ __align__(16) __half g_WtH[N_DIM * K1];         // W^T fp16 [n][k]
__device__ __align__(16) __half g_XtH[(long)N_DIM * M_DIM];// X^T fp16 [n][m] (4 MB)

#define NTHREADS 512
#define BK 64
#define STAGES 4
#define ROW_B 144                                 // 128 B data + 16 B pad
#define TILE_B (128 * ROW_B)                      // 18432 B per tile
#define SMEM_BYTES (STAGES * 2 * TILE_B)          // 147456 B

#define ITERS_PER_MT 256                          // 16384 / BK
#define TOTAL_ITERS  (128 * ITERS_PER_MT)         // 32768
#define IPC          222                          // ceil(32768/148)
#define GRID2        148

// ---------------- helpers ----------------
__device__ __forceinline__ uint32_t smem_u32(const void* p) {
    uint32_t a;
    asm("{ .reg .u64 t; cvta.to.shared.u64 t, %1; cvt.u32.u64 %0, t; }"
        : "=r"(a) : "l"(p));
    return a;
}
#define CP_ASYNC16(dst, src) \
    asm volatile("cp.async.cg.shared.global [%0], [%1], 16;" :: "r"(dst), "l"(src) : "memory")
#define CP_COMMIT()  asm volatile("cp.async.commit_group;" ::: "memory")
#define CP_WAIT2()   asm volatile("cp.async.wait_group 2;" ::: "memory")
#define CP_WAIT0()   asm volatile("cp.async.wait_group 0;" ::: "memory")

__device__ __forceinline__ void mma_f16(float c[4], const uint32_t a[4], const uint32_t b[2]) {
    asm volatile(
        "mma.sync.aligned.m16n8k16.row.col.f32.f16.f16.f32 "
        "{%0,%1,%2,%3}, {%4,%5,%6,%7}, {%8,%9}, {%0,%1,%2,%3};"
        : "+f"(c[0]), "+f"(c[1]), "+f"(c[2]), "+f"(c[3])
        : "r"(a[0]), "r"(a[1]), "r"(a[2]), "r"(a[3]), "r"(b[0]), "r"(b[1]));
}
__device__ __forceinline__ void ldsm4(uint32_t r[4], uint32_t addr) {
    asm volatile("ldmatrix.sync.aligned.m8n8.x4.shared.b16 {%0,%1,%2,%3}, [%4];"
                 : "=r"(r[0]), "=r"(r[1]), "=r"(r[2]), "=r"(r[3]) : "r"(addr));
}
__device__ __forceinline__ uint32_t pack_h2(float x, float y) {
    __half2 h = __float22half2_rn(make_float2(x, y));
    return *(uint32_t*)&h;
}
__device__ __forceinline__ void red_add_v2(float* p, float x, float y) {
    asm volatile("red.global.add.v2.f32 [%0], {%1, %2};"
                 :: "l"(p), "f"(x), "f"(y) : "memory");
}

// ---------------- producers ----------------
__device__ __forceinline__ void load_B_tile(
    uint32_t ts, const __half* __restrict__ T, long ldt, int k0, int tid)
{
    #pragma unroll
    for (int j = 0; j < 2; j++) {
        int idx = tid + j * NTHREADS;          // 0..1023
        int row = idx >> 3, cc = idx & 7;
        CP_ASYNC16(ts + (uint32_t)(row * ROW_B + cc * 16),
                   T + (long)row * ldt + k0 + cc * 8);
    }
}
__device__ __forceinline__ void ldg_A(float4 rb[4], const float* __restrict__ A,
                                      long lda, int k0, int tid)
{
    const float* p = A + (long)(tid >> 2) * lda + k0 + (tid & 3) * 16;
    #pragma unroll
    for (int q = 0; q < 4; q++) rb[q] = *(const float4*)(p + q * 4);
}
__device__ __forceinline__ void sts_A_cvt(uint32_t as, const float4 rb[4], int tid)
{
    int row = tid >> 2, c = tid & 3;
    int s = (row >> 3) & 3;
    uint32_t off = as + (uint32_t)(row * ROW_B + ((c ^ s) * 32));
    uint32_t p0 = pack_h2(rb[0].x, rb[0].y), p1 = pack_h2(rb[0].z, rb[0].w);
    uint32_t p2 = pack_h2(rb[1].x, rb[1].y), p3 = pack_h2(rb[1].z, rb[1].w);
    uint32_t p4 = pack_h2(rb[2].x, rb[2].y), p5 = pack_h2(rb[2].z, rb[2].w);
    uint32_t p6 = pack_h2(rb[3].x, rb[3].y), p7 = pack_h2(rb[3].z, rb[3].w);
    asm volatile("st.shared.v4.b32 [%0], {%1,%2,%3,%4};"
                 :: "r"(off), "r"(p0), "r"(p1), "r"(p2), "r"(p3) : "memory");
    asm volatile("st.shared.v4.b32 [%0], {%1,%2,%3,%4};"
                 :: "r"(off + 16), "r"(p4), "r"(p5), "r"(p6), "r"(p7) : "memory");
}

// ---------------- compute ----------------
__device__ __forceinline__ void compute_stage(
    uint32_t sA, uint32_t sB,
    uint32_t Aoff0, uint32_t Aoff1, uint32_t sft0, uint32_t sft1,
    uint32_t Boff, float acc[2][4][4])
{
    #pragma unroll
    for (int kk = 0; kk < 4; kk++) {
        uint32_t a[2][4], b[2][4];
        ldsm4(a[0], sA + Aoff0 + (((uint32_t)(kk << 5)) ^ sft0));
        ldsm4(a[1], sA + Aoff1 + (((uint32_t)(kk << 5)) ^ sft1));
        ldsm4(b[0], sB + Boff + kk * 32);
        ldsm4(b[1], sB + Boff + 16 * ROW_B + kk * 32);
        #pragma unroll
        for (int mt = 0; mt < 2; mt++)
            #pragma unroll
            for (int nt = 0; nt < 4; nt++)
                mma_f16(acc[mt][nt], a[mt], &b[nt >> 1][(nt & 1) * 2]);
    }
}

// ---------------- mainloop (runtime NITER; B stage s in group g_s) ----------
__device__ __forceinline__ void gemm_mainloop(
    const float* __restrict__ A, long lda,
    const __half* __restrict__ B, long ldb,
    int NITER, float acc[2][4][4], char* smem)
{
    const int tid = threadIdx.x;
    const int wid = tid >> 5, lid = tid & 31;
    const int wr = wid >> 2, wc = wid & 3;
    const uint32_t sbase = smem_u32(smem);
    const uint32_t bregion = sbase + STAGES * TILE_B;

    const int row0 = wr * 32 + (lid & 15);
    const int row1 = row0 + 16;
    const uint32_t sub16 = ((lid >> 4) & 1) * 16;
    const uint32_t Aoff0 = (uint32_t)(row0 * ROW_B) + sub16;
    const uint32_t Aoff1 = (uint32_t)(row1 * ROW_B) + sub16;
    const uint32_t sft0 = (uint32_t)(((row0 >> 3) & 3) << 5);
    const uint32_t sft1 = (uint32_t)(((row1 >> 3) & 3) << 5);
    const uint32_t Boff = (uint32_t)((wc * 32 + ((lid >> 4) & 1) * 8 + (lid & 7)) * ROW_B
                                     + ((lid >> 3) & 1) * 16);

    #pragma unroll
    for (int mt = 0; mt < 2; mt++)
        #pragma unroll
        for (int nt = 0; nt < 4; nt++)
            #pragma unroll
            for (int r = 0; r < 4; r++) acc[mt][nt][r] = 0.0f;

    float4 rb[4];

    // Prologue: B_s committed in group g_s; A stage0 in smem; rb = A1.
    ldg_A(rb, A, lda, 0, tid);
    load_B_tile(bregion, B, ldb, 0, tid);
    CP_COMMIT();                               // g0 = B0
    sts_A_cvt(sbase, rb, tid);
    ldg_A(rb, A, lda, BK, tid);
    if (1 < NITER) load_B_tile(bregion + TILE_B, B, ldb, BK, tid);
    CP_COMMIT();                               // g1 = B1
    if (2 < NITER) load_B_tile(bregion + 2 * TILE_B, B, ldb, 2 * BK, tid);
    CP_COMMIT();                               // g2 = B2
    CP_WAIT2();                                // B0 resident
    __syncthreads();

    #pragma unroll 1
    for (int i = 0; i < NITER; i++) {
        if (i + 1 < NITER)
            sts_A_cvt(sbase + ((i + 1) % STAGES) * TILE_B, rb, tid);
        if (i + 2 < NITER)
            ldg_A(rb, A, lda, (i + 2) * BK, tid);
        if (i + 3 < NITER)
            load_B_tile(bregion + ((i + 3) % STAGES) * TILE_B, B, ldb, (i + 3) * BK, tid);
        CP_COMMIT();                           // g_{i+3}
        int s = i % STAGES;
        compute_stage(sbase + s * TILE_B, bregion + s * TILE_B,
                      Aoff0, Aoff1, sft0, sft1, Boff, acc);
        if (i + 1 < NITER) { CP_WAIT2(); }     // B_{i+1} resident
        else               { CP_WAIT0(); }
        __syncthreads();
    }
}

// ---------------- prep: W^T fp16 + zero out ----------------
__global__ __launch_bounds__(256) void prep_kernel(const float* __restrict__ w,
                                                   float* __restrict__ out) {
    const long gi = (long)blockIdx.x * blockDim.x + threadIdx.x;
    if (gi < N_DIM * K1) {
        int n = (int)(gi / K1), k = (int)(gi % K1);
        g_WtH[gi] = __float2half_rn(w[(long)k * N_DIM + n]);
    }
    const long n4 = (long)M_DIM * N_DIM / 4;
    for (long i = gi; i < n4; i += (long)gridDim.x * blockDim.x)
        ((float4*)out)[i] = make_float4(0.f, 0.f, 0.f, 0.f);
}

// ---------------- GEMM1: XtH = (inputs @ W)^T fp16 ----------------
__global__ __launch_bounds__(NTHREADS, 1) void gemm1_kernel(const float* __restrict__ inputs) {
    extern __shared__ char smem[];
    float acc[2][4][4];
    const int m0 = blockIdx.x * 128;

    gemm_mainloop(inputs + (long)m0 * K1, K1, g_WtH, K1, K1 / BK, acc, smem);

    const int wid = threadIdx.x >> 5, lid = threadIdx.x & 31;
    const int wr = wid >> 2, wc = wid & 3, gID = lid >> 2, tig = lid & 3;
    #pragma unroll
    for (int mt = 0; mt < 2; mt++)
        #pragma unroll
        for (int nt = 0; nt < 4; nt++) {
            int r = m0 + wr * 32 + mt * 16 + gID;
            int c = wc * 32 + nt * 8 + tig * 2;
            g_XtH[(long)c * M_DIM + r]           = __float2half_rn(acc[mt][nt][0]);
            g_XtH[(long)(c + 1) * M_DIM + r]     = __float2half_rn(acc[mt][nt][1]);
            g_XtH[(long)c * M_DIM + r + 8]       = __float2half_rn(acc[mt][nt][2]);
            g_XtH[(long)(c + 1) * M_DIM + r + 8] = __float2half_rn(acc[mt][nt][3]);
        }
}

// ---------------- GEMM2: static contiguous ranges, RED epilogue -------------
__global__ __launch_bounds__(NTHREADS, 1) void gemm2_kernel(const float* __restrict__ adj,
                                                            float* __restrict__ out) {
    extern __shared__ char smem[];
    float acc[2][4][4];

    const int tid = threadIdx.x;
    const int wid = tid >> 5, lid = tid & 31;
    const int wr = wid >> 2, wc = wid & 3, gID = lid >> 2, tig = lid & 3;

    long gstart = (long)blockIdx.x * IPC;
    long gend = gstart + IPC;
    if (gend > TOTAL_ITERS) gend = TOTAL_ITERS;

    while (gstart < gend) {
        const int mt_tile = (int)(gstart >> 8);          // / ITERS_PER_MT
        const int ki0     = (int)(gstart & 255);
        int seg = (int)(gend - gstart);
        if (seg > ITERS_PER_MT - ki0) seg = ITERS_PER_MT - ki0;

        const long m0 = (long)mt_tile * 128;
        const long k0 = (long)ki0 * BK;

        gemm_mainloop(adj + m0 * M_DIM + k0, M_DIM,
                      g_XtH + k0, M_DIM, seg, acc, smem);

        #pragma unroll
        for (int mt = 0; mt < 2; mt++)
            #pragma unroll
            for (int nt = 0; nt < 4; nt++) {
                long r = m0 + wr * 32 + mt * 16 + gID;
                int  c = wc * 32 + nt * 8 + tig * 2;
                red_add_v2(&out[r * N_DIM + c],       acc[mt][nt][0], acc[mt][nt][1]);
                red_add_v2(&out[(r + 8) * N_DIM + c], acc[mt][nt][2], acc[mt][nt][3]);
            }
        gstart += seg;
    }
}

// ---------------- launch ----------------
extern "C" void kernel_launch(void* const* d_in, const int* in_sizes, int n_in,
                              void* d_out, int out_size)
{
    const float* inputs  = (const float*)d_in[0];
    const float* adj     = (const float*)d_in[1];
    const float* weights = (const float*)d_in[2];
    float* out = (float*)d_out;

    cudaFuncSetAttribute(gemm1_kernel, cudaFuncAttributeMaxDynamicSharedMemorySize, SMEM_BYTES);
    cudaFuncSetAttribute(gemm2_kernel, cudaFuncAttributeMaxDynamicSharedMemorySize, SMEM_BYTES);

    prep_kernel<<<512, 256>>>(weights, out);
    gemm1_kernel<<<M_DIM / 128, NTHREADS, SMEM_BYTES>>>(inputs);
    gemm2_kernel<<<GRID2, NTHREADS, SMEM_BYTES>>>(adj, out);
}